// round 5
// baseline (speedup 1.0000x reference)
#include <cuda_runtime.h>
#include <math.h>

typedef unsigned long long ull;
#define NCTA 132

// ---------------- persistent device state (no allocations) -----------------
__device__ float g_WallT[512 * 2560];   // [k][col]; cols 0..2047 gates (j'=4u+g), 2048..2559 W1
__device__ float g_ball[2560];          // matching biases
__device__ float g_W2T[512 * 9];        // [k][out]
__device__ float g_h[2][256 * 512];
__device__ float g_c[256 * 512];
__device__ float g_zz[2][256 * 512];
__device__ unsigned g_arrive;
__device__ volatile unsigned g_epoch;

// ---------------- helpers ----------------------------------------------------
__device__ __forceinline__ ull ffma2(ull a, ull b, ull c) {
    ull d; asm("fma.rn.f32x2 %0,%1,%2,%3;" : "=l"(d) : "l"(a), "l"(b), "l"(c)); return d;
}
__device__ __forceinline__ ull dup2(float v) {
    ull d; asm("mov.b64 %0,{%1,%1};" : "=l"(d) : "f"(v)); return d;
}
__device__ __forceinline__ float sigf(float v) { return 1.f / (1.f + expf(-v)); }

__device__ __forceinline__ void gbar(int p) {
    __syncthreads();
    if (threadIdx.x == 0) {
        __threadfence();
        unsigned prev = atomicAdd(&g_arrive, 1u);
        if (prev == NCTA - 1) {
            g_arrive = 0;
            __threadfence();
            g_epoch = (unsigned)p;
        } else {
            while (g_epoch < (unsigned)p) __nanosleep(32);
            __threadfence();
        }
    }
    __syncthreads();
}

// ---------------- prep kernels -----------------------------------------------
__global__ void prepWall(const float* __restrict__ Wih, const float* __restrict__ Whh,
                         const float* __restrict__ W1) {
    int idx = blockIdx.x * 256 + threadIdx.x;           // 1,310,720 total
    int k = idx / 2560, col = idx - k * 2560;
    float v;
    if (col < 2048) { int u = col >> 2, gi = col & 3, j = gi * 512 + u;
                      v = Wih[j * 512 + k] + Whh[j * 512 + k]; }
    else            { v = W1[(col - 2048) * 512 + k]; }
    g_WallT[idx] = v;
}
__global__ void prepB(const float* __restrict__ bih, const float* __restrict__ bhh,
                      const float* __restrict__ b1, const float* __restrict__ W2) {
    int idx = blockIdx.x * 256 + threadIdx.x;           // 7168 total
    if (idx < 2048) { int u = idx >> 2, gi = idx & 3, j = gi * 512 + u;
                      g_ball[idx] = bih[j] + bhh[j]; }
    else if (idx < 2560) g_ball[idx] = b1[idx - 2048];
    else if (idx < 7168) { int i2 = idx - 2560; int k = i2 / 9, o = i2 - k * 9;
                           g_W2T[i2] = W2[o * 512 + k]; }
    if (idx == 0) { g_arrive = 0; g_epoch = 0; }
}

// ---------------- step 0: h(1), c(1) = cell(x, hx0, cx0), K=1024 --------------
__global__ void __launch_bounds__(256) step0_kernel(
    const float* __restrict__ x, const float* __restrict__ hx0,
    const float* __restrict__ cx0,
    const float* __restrict__ Wih, const float* __restrict__ Whh) {
    __shared__ __align__(16) float As[32 * 64];
    __shared__ __align__(16) float Wsm[32 * 64];
    const int tid = threadIdx.x, tx = tid & 15, ty = tid >> 4;
    const int ct = blockIdx.x, rb = (ct >> 5) << 6, cb = (ct & 31) << 6;
    const int r = tid & 63, s = tid >> 6;
    const int jc = cb + r, jrow = (jc & 3) * 512 + (jc >> 2);

    float acc[4][4] = {};
    for (int kc = 0; kc < 1024; kc += 32) {
        const float* Asrc = (kc < 512) ? x : hx0;
        const float* Wsrc = (kc < 512) ? Wih : Whh;
        const int kloc = (kc < 512) ? kc : kc - 512;
        __syncthreads();
#pragma unroll
        for (int h = 0; h < 2; ++h) {
            int sl = s + h * 4;
            float4 v = *(const float4*)(Asrc + (rb + r) * 512 + kloc + sl * 4);
            As[(sl * 4 + 0) * 64 + r] = v.x; As[(sl * 4 + 1) * 64 + r] = v.y;
            As[(sl * 4 + 2) * 64 + r] = v.z; As[(sl * 4 + 3) * 64 + r] = v.w;
            float4 w = *(const float4*)(Wsrc + jrow * 512 + kloc + sl * 4);
            Wsm[(sl * 4 + 0) * 64 + r] = w.x; Wsm[(sl * 4 + 1) * 64 + r] = w.y;
            Wsm[(sl * 4 + 2) * 64 + r] = w.z; Wsm[(sl * 4 + 3) * 64 + r] = w.w;
        }
        __syncthreads();
#pragma unroll 8
        for (int k = 0; k < 32; ++k) {
            float a0 = As[k * 64 + ty * 4 + 0], a1 = As[k * 64 + ty * 4 + 1];
            float a2 = As[k * 64 + ty * 4 + 2], a3 = As[k * 64 + ty * 4 + 3];
            float w0 = Wsm[k * 64 + tx * 4 + 0], w1 = Wsm[k * 64 + tx * 4 + 1];
            float w2 = Wsm[k * 64 + tx * 4 + 2], w3 = Wsm[k * 64 + tx * 4 + 3];
            acc[0][0] += a0 * w0; acc[0][1] += a0 * w1; acc[0][2] += a0 * w2; acc[0][3] += a0 * w3;
            acc[1][0] += a1 * w0; acc[1][1] += a1 * w1; acc[1][2] += a1 * w2; acc[1][3] += a1 * w3;
            acc[2][0] += a2 * w0; acc[2][1] += a2 * w1; acc[2][2] += a2 * w2; acc[2][3] += a2 * w3;
            acc[3][0] += a3 * w0; acc[3][1] += a3 * w1; acc[3][2] += a3 * w2; acc[3][3] += a3 * w3;
        }
    }
    const int u = (cb >> 2) + tx;
#pragma unroll
    for (int i = 0; i < 4; ++i) {
        int gx = (rb + ty * 4 + i) * 512 + u;
        float vi = sigf(acc[i][0] + g_ball[cb + tx * 4 + 0]);
        float vf = sigf(acc[i][1] + g_ball[cb + tx * 4 + 1]);
        float vg = tanhf(acc[i][2] + g_ball[cb + tx * 4 + 2]);
        float vo = sigf(acc[i][3] + g_ball[cb + tx * 4 + 3]);
        float cn = vf * cx0[gx] + vi * vg;
        g_c[gx] = cn;
        g_h[1][gx] = vo * tanhf(cn);
    }
}

// ---------------- persistent main kernel --------------------------------------
__global__ void __launch_bounds__(256) main_kernel(float* __restrict__ out,
                                                   const float* __restrict__ b2) {
    __shared__ __align__(16) float sm[9728];  // compute: As[0..2047] Ws[2048..4607] Cs[4608..9727]
    __shared__ float bsm[80];                 // y-CTAs : Zs[0..4159]  W2s[4160..8767]
    const int tid = threadIdx.x, ct = blockIdx.x;

    if (ct < 128) {
        float* As = sm; float* Ws = sm + 2048; float* Cs = sm + 4608;
        const int rb = (ct >> 5) << 6, cs = ct & 31, cb = cs * 80;
        const int tx = tid & 15, ty = tid >> 4, ty4 = ty * 4, tx5 = tx * 5;
        const int r = tid & 63, s = tid >> 6;
        const int nU   = (cs < 25) ? 20 : (cs == 25 ? 12 : 0);
        const int zlc0 = (cs < 25) ? 80 : (cs == 25 ? 48 : 0);
        const int nZ = 80 - zlc0;
        const int erow = tid >> 2, eq = tid & 3;
        const int ub = cb >> 2;

        int offs[10], soff[10];
#pragma unroll
        for (int i = 0; i < 10; ++i) {
            int q = tid * 10 + i, kk = q / 80, cc = q - kk * 80;
            offs[i] = kk * 2560 + cc; soff[i] = kk * 80 + cc;
        }
        if (tid < 80) bsm[tid] = g_ball[cb + tid];
        __syncthreads();

        for (int t = 1; t <= 327; ++t) {
            if (t <= 326 && (t <= 325 || nZ > 0)) {
                const float* hc = g_h[t & 1];
                const float* ab = hc + (rb + r) * 512 + s * 4;
                float aR[8], wR[10];
                {   float4 v0 = *(const float4*)(ab), v1 = *(const float4*)(ab + 16);
                    aR[0]=v0.x; aR[1]=v0.y; aR[2]=v0.z; aR[3]=v0.w;
                    aR[4]=v1.x; aR[5]=v1.y; aR[6]=v1.z; aR[7]=v1.w;
#pragma unroll
                    for (int i = 0; i < 10; ++i) wR[i] = g_WallT[cb + offs[i]]; }
                ull acc0[5] = {0,0,0,0,0}, acc1[5] = {0,0,0,0,0};
                for (int kc = 0; kc < 512; kc += 32) {
                    __syncthreads();
#pragma unroll
                    for (int j = 0; j < 4; ++j) {
                        As[(s * 4 + j) * 64 + r] = aR[j];
                        As[(s * 4 + 16 + j) * 64 + r] = aR[4 + j];
                    }
#pragma unroll
                    for (int i = 0; i < 10; ++i) Ws[soff[i]] = wR[i];
                    __syncthreads();
                    if (kc < 480) {
                        float4 v0 = *(const float4*)(ab + kc + 32);
                        float4 v1 = *(const float4*)(ab + kc + 48);
                        aR[0]=v0.x; aR[1]=v0.y; aR[2]=v0.z; aR[3]=v0.w;
                        aR[4]=v1.x; aR[5]=v1.y; aR[6]=v1.z; aR[7]=v1.w;
                        const float* wb = g_WallT + (kc + 32) * 2560 + cb;
#pragma unroll
                        for (int i = 0; i < 10; ++i) wR[i] = wb[offs[i]];
                    }
#pragma unroll 4
                    for (int k = 0; k < 32; ++k) {
                        ull a01 = *(const ull*)(As + k * 64 + ty4);
                        ull a23 = *(const ull*)(As + k * 64 + ty4 + 2);
                        const float* wp = Ws + k * 80 + tx5;
#pragma unroll
                        for (int i = 0; i < 5; ++i) {
                            ull wd = dup2(wp[i]);
                            acc0[i] = ffma2(a01, wd, acc0[i]);
                            acc1[i] = ffma2(a23, wd, acc1[i]);
                        }
                    }
                }
#pragma unroll
                for (int i = 0; i < 5; ++i) {
                    float lo, hi;
                    asm("mov.b64 {%0,%1},%2;" : "=f"(lo), "=f"(hi) : "l"(acc0[i]));
                    Cs[(ty4 + 0) * 80 + tx5 + i] = lo;
                    Cs[(ty4 + 1) * 80 + tx5 + i] = hi;
                    asm("mov.b64 {%0,%1},%2;" : "=f"(lo), "=f"(hi) : "l"(acc1[i]));
                    Cs[(ty4 + 2) * 80 + tx5 + i] = lo;
                    Cs[(ty4 + 3) * 80 + tx5 + i] = hi;
                }
                __syncthreads();
                if (t <= 325) {
                    float* hn = g_h[(t + 1) & 1];
#pragma unroll
                    for (int j = 0; j < 5; ++j) {
                        int iu = eq + 4 * j;
                        if (iu < nU) {
                            int lc = iu * 4;
                            float vi = sigf(Cs[erow * 80 + lc + 0] + bsm[lc + 0]);
                            float vf = sigf(Cs[erow * 80 + lc + 1] + bsm[lc + 1]);
                            float vg = tanhf(Cs[erow * 80 + lc + 2] + bsm[lc + 2]);
                            float vo = sigf(Cs[erow * 80 + lc + 3] + bsm[lc + 3]);
                            int gx = (rb + erow) * 512 + ub + iu;
                            float cn = vf * g_c[gx] + vi * vg;
                            g_c[gx] = cn;
                            hn[gx] = vo * tanhf(cn);
                        }
                    }
                }
                if (nZ > 0) {
                    float* zn = g_zz[t & 1];
#pragma unroll
                    for (int j = 0; j < 20; ++j) {
                        int ic = eq + 4 * j;
                        if (ic < nZ) {
                            int lc = zlc0 + ic;
                            float v = Cs[erow * 80 + lc] + bsm[lc];
                            zn[(rb + erow) * 512 + (cb + lc - 2048)] = v > 0.f ? v : 0.f;
                        }
                    }
                }
            }
            gbar(t);
        }
    } else {
        // ---- y-CTAs: y(t-1) = z(t-1) @ W2^T + b2 ----
        float* Zs = sm; float* W2s = sm + 4160;   // Zs padded: [64][65]
        const int rbY = (ct - 128) * 64;
        const int r = tid & 63, s = tid >> 6;
        for (int i = tid; i < 4608; i += 256) W2s[i] = g_W2T[i];
        __syncthreads();
        for (int t = 1; t <= 327; ++t) {
            if (t >= 2) {
                const float* z = g_zz[(t - 1) & 1];
                float acc[3] = {0.f, 0.f, 0.f};
                for (int kc = 0; kc < 512; kc += 64) {
                    __syncthreads();
#pragma unroll
                    for (int h = 0; h < 4; ++h) {
                        int sl = s + h * 4;
                        float4 v = *(const float4*)(z + (rbY + r) * 512 + kc + sl * 4);
                        Zs[r * 65 + sl * 4 + 0] = v.x; Zs[r * 65 + sl * 4 + 1] = v.y;
                        Zs[r * 65 + sl * 4 + 2] = v.z; Zs[r * 65 + sl * 4 + 3] = v.w;
                    }
                    __syncthreads();
#pragma unroll
                    for (int pi = 0; pi < 3; ++pi) {
                        int p = tid + pi * 256;
                        if (p < 576) {
                            int rw = p / 9, o = p - rw * 9;
                            float a = acc[pi];
#pragma unroll 8
                            for (int k = 0; k < 64; ++k)
                                a += Zs[rw * 65 + k] * W2s[(kc + k) * 9 + o];
                            acc[pi] = a;
                        }
                    }
                }
#pragma unroll
                for (int pi = 0; pi < 3; ++pi) {
                    int p = tid + pi * 256;
                    if (p < 576) {
                        int rw = p / 9, o = p - rw * 9;
                        out[(rbY + rw) * 2934 + (t - 2) * 9 + o] = acc[pi] + b2[o];
                    }
                }
            }
            gbar(t);
        }
    }
}

// ---------------- launch -------------------------------------------------------
extern "C" void kernel_launch(void* const* d_in, const int* in_sizes, int n_in,
                              void* d_out, int out_size) {
    const float* x   = (const float*)d_in[0];
    const float* hx0 = (const float*)d_in[1];
    const float* cx0 = (const float*)d_in[2];
    const float* Wih = (const float*)d_in[3];
    const float* Whh = (const float*)d_in[4];
    const float* bih = (const float*)d_in[5];
    const float* bhh = (const float*)d_in[6];
    const float* W1  = (const float*)d_in[7];
    const float* b1  = (const float*)d_in[8];
    const float* W2  = (const float*)d_in[9];
    const float* b2  = (const float*)d_in[10];
    float* out = (float*)d_out;

    prepB<<<28, 256>>>(bih, bhh, b1, W2);
    prepWall<<<5120, 256>>>(Wih, Whh, W1);
    step0_kernel<<<128, 256>>>(x, hx0, cx0, Wih, Whh);
    main_kernel<<<NCTA, 256>>>(out, b2);
}

// round 6
// speedup vs baseline: 1.1758x; 1.1758x over previous
#include <cuda_runtime.h>
#include <math.h>

typedef unsigned long long ull;
#define NCTA 132
// dynamic smem layout (float offsets)
#define SMA 40960   // A double buffer: 2 x 16kp x 128
#define SMC 45056   // C tile 64 x 81
#define SMB 50240   // bias 80
#define SMEM_BYTES 201280

// ---------------- persistent device state (no allocations) -----------------
__device__ float g_Wpair[512 * 2560];   // [kp][col*2+d]: k=2kp+d; cols 0..2047 gates (j'=4u+g), 2048..2559 W1
__device__ float g_ball[2560];
__device__ float g_W2T[512 * 9];
__device__ float g_h[2][256 * 512];
__device__ float g_c[256 * 512];
__device__ float g_zz[2][256 * 512];
__device__ unsigned g_arrive;
__device__ volatile unsigned g_epoch;

// ---------------- helpers ----------------------------------------------------
__device__ __forceinline__ ull ffma2(ull a, ull b, ull c) {
    ull d; asm("fma.rn.f32x2 %0,%1,%2,%3;" : "=l"(d) : "l"(a), "l"(b), "l"(c)); return d;
}
__device__ __forceinline__ float psum(ull v) {
    float lo, hi; asm("mov.b64 {%0,%1},%2;" : "=f"(lo), "=f"(hi) : "l"(v)); return lo + hi;
}
__device__ __forceinline__ float sigf(float v) { return 1.f / (1.f + expf(-v)); }

__device__ __forceinline__ void gbar(int p) {
    __syncthreads();
    if (threadIdx.x == 0) {
        __threadfence();
        unsigned prev = atomicAdd(&g_arrive, 1u);
        if (prev == NCTA - 1) {
            g_arrive = 0;
            __threadfence();
            g_epoch = (unsigned)p;
        } else {
            while (g_epoch < (unsigned)p) __nanosleep(32);
            __threadfence();
        }
    }
    __syncthreads();
}

// ---------------- prep kernels -----------------------------------------------
__global__ void prepWpair(const float* __restrict__ Wih, const float* __restrict__ Whh,
                          const float* __restrict__ W1) {
    int idx = blockIdx.x * 256 + threadIdx.x;        // 1,310,720
    int kp = idx / 5120, rem = idx - kp * 5120;
    int col = rem >> 1, d = rem & 1;
    int k = kp * 2 + d;
    float v;
    if (col < 2048) { int u = col >> 2, gi = col & 3, j = gi * 512 + u;
                      v = Wih[j * 512 + k] + Whh[j * 512 + k]; }
    else            { v = W1[(col - 2048) * 512 + k]; }
    g_Wpair[idx] = v;
}
__global__ void prepB(const float* __restrict__ bih, const float* __restrict__ bhh,
                      const float* __restrict__ b1, const float* __restrict__ W2) {
    int idx = blockIdx.x * 256 + threadIdx.x;        // 7168
    if (idx < 2048) { int u = idx >> 2, gi = idx & 3, j = gi * 512 + u;
                      g_ball[idx] = bih[j] + bhh[j]; }
    else if (idx < 2560) g_ball[idx] = b1[idx - 2048];
    else if (idx < 7168) { int i2 = idx - 2560; int k = i2 / 9, o = i2 - k * 9;
                           g_W2T[i2] = W2[o * 512 + k]; }
    if (idx == 0) { g_arrive = 0; g_epoch = 0; }
}

// ---------------- step 0: h(1), c(1) = cell(x, hx0, cx0), K=1024 --------------
__global__ void __launch_bounds__(256) step0_kernel(
    const float* __restrict__ x, const float* __restrict__ hx0,
    const float* __restrict__ cx0,
    const float* __restrict__ Wih, const float* __restrict__ Whh) {
    __shared__ __align__(16) float As[32 * 64];
    __shared__ __align__(16) float Wsm[32 * 64];
    const int tid = threadIdx.x, tx = tid & 15, ty = tid >> 4;
    const int ct = blockIdx.x, rb = (ct >> 5) << 6, cb = (ct & 31) << 6;
    const int r = tid & 63, s = tid >> 6;
    const int jc = cb + r, jrow = (jc & 3) * 512 + (jc >> 2);

    float acc[4][4] = {};
    for (int kc = 0; kc < 1024; kc += 32) {
        const float* Asrc = (kc < 512) ? x : hx0;
        const float* Wsrc = (kc < 512) ? Wih : Whh;
        const int kloc = (kc < 512) ? kc : kc - 512;
        __syncthreads();
#pragma unroll
        for (int h = 0; h < 2; ++h) {
            int sl = s + h * 4;
            float4 v = *(const float4*)(Asrc + (rb + r) * 512 + kloc + sl * 4);
            As[(sl * 4 + 0) * 64 + r] = v.x; As[(sl * 4 + 1) * 64 + r] = v.y;
            As[(sl * 4 + 2) * 64 + r] = v.z; As[(sl * 4 + 3) * 64 + r] = v.w;
            float4 w = *(const float4*)(Wsrc + jrow * 512 + kloc + sl * 4);
            Wsm[(sl * 4 + 0) * 64 + r] = w.x; Wsm[(sl * 4 + 1) * 64 + r] = w.y;
            Wsm[(sl * 4 + 2) * 64 + r] = w.z; Wsm[(sl * 4 + 3) * 64 + r] = w.w;
        }
        __syncthreads();
#pragma unroll 8
        for (int k = 0; k < 32; ++k) {
            float a0 = As[k * 64 + ty * 4 + 0], a1 = As[k * 64 + ty * 4 + 1];
            float a2 = As[k * 64 + ty * 4 + 2], a3 = As[k * 64 + ty * 4 + 3];
            float w0 = Wsm[k * 64 + tx * 4 + 0], w1 = Wsm[k * 64 + tx * 4 + 1];
            float w2 = Wsm[k * 64 + tx * 4 + 2], w3 = Wsm[k * 64 + tx * 4 + 3];
            acc[0][0] += a0 * w0; acc[0][1] += a0 * w1; acc[0][2] += a0 * w2; acc[0][3] += a0 * w3;
            acc[1][0] += a1 * w0; acc[1][1] += a1 * w1; acc[1][2] += a1 * w2; acc[1][3] += a1 * w3;
            acc[2][0] += a2 * w0; acc[2][1] += a2 * w1; acc[2][2] += a2 * w2; acc[2][3] += a2 * w3;
            acc[3][0] += a3 * w0; acc[3][1] += a3 * w1; acc[3][2] += a3 * w2; acc[3][3] += a3 * w3;
        }
    }
    const int u = (cb >> 2) + tx;
#pragma unroll
    for (int i = 0; i < 4; ++i) {
        int gx = (rb + ty * 4 + i) * 512 + u;
        float vi = sigf(acc[i][0] + g_ball[cb + tx * 4 + 0]);
        float vf = sigf(acc[i][1] + g_ball[cb + tx * 4 + 1]);
        float vg = tanhf(acc[i][2] + g_ball[cb + tx * 4 + 2]);
        float vo = sigf(acc[i][3] + g_ball[cb + tx * 4 + 3]);
        float cn = vf * cx0[gx] + vi * vg;
        g_c[gx] = cn;
        g_h[1][gx] = vo * tanhf(cn);
    }
}

// ---------------- persistent main kernel --------------------------------------
__global__ void __launch_bounds__(256) main_kernel(float* __restrict__ out,
                                                   const float* __restrict__ b2) {
    extern __shared__ float sm[];
    const int tid = threadIdx.x, ct = blockIdx.x;

    if (ct < 128) {
        const int rb = (ct >> 5) << 6, cs = ct & 31, cb = cs * 80;
        const int lane = tid & 31, warp = tid >> 5, c0 = warp * 10;
        const int nU   = (cs < 25) ? 20 : (cs == 25 ? 12 : 0);
        const int zlc0 = (cs < 25) ? 80 : (cs == 25 ? 48 : 0);
        const int nZ = 80 - zlc0;
        const int erow = tid >> 2, eq = tid & 3, ub = cb >> 2;
        const int rr = tid >> 2, kq = (tid & 3) * 8;
        const int sidx = (tid & 3) * 4 * 64 + rr;

        // one-time: load W tile (80 cols x 512 k, k-pair layout) into smem
        for (int i = tid; i < 10240; i += 256) {
            int kp = i / 40, off = i - kp * 40;
            ((float4*)sm)[kp * 40 + off] =
                ((const float4*)(g_Wpair + kp * 5120 + cb * 2))[off];
        }
        if (tid < 80) sm[SMB + tid] = g_ball[cb + tid];
        __syncthreads();

        for (int t = 1; t <= 327; ++t) {
            if (t <= 326 && (t <= 325 || nZ > 0)) {
                const float* hc = g_h[t & 1] + (rb + rr) * 512 + kq;
                ull acc[20];
#pragma unroll
                for (int i = 0; i < 20; ++i) acc[i] = 0ull;

                float4 v0 = *(const float4*)(hc);
                float4 v1 = *(const float4*)(hc + 4);
                {
                    float2* Ab = (float2*)(sm + SMA);
                    Ab[sidx]       = make_float2(v0.x, v0.y);
                    Ab[sidx + 64]  = make_float2(v0.z, v0.w);
                    Ab[sidx + 128] = make_float2(v1.x, v1.y);
                    Ab[sidx + 192] = make_float2(v1.z, v1.w);
                }
                for (int c = 0; c < 16; ++c) {
                    __syncthreads();
                    if (c < 15) {
                        v0 = *(const float4*)(hc + (c + 1) * 32);
                        v1 = *(const float4*)(hc + (c + 1) * 32 + 4);
                    }
                    const ull* Ap = (const ull*)(sm + SMA + (c & 1) * 2048);
                    const float* Wb = sm + c * 2560 + c0 * 2;   // c*16*160
#pragma unroll
                    for (int kp = 0; kp < 16; ++kp) {
                        ull a0 = Ap[kp * 64 + lane];
                        ull a1 = Ap[kp * 64 + 32 + lane];
                        const ulonglong2* Wp = (const ulonglong2*)(Wb + kp * 160);
                        ulonglong2 wA = Wp[0], wB = Wp[1], wC = Wp[2], wD = Wp[3], wE = Wp[4];
                        acc[0] = ffma2(a0, wA.x, acc[0]);  acc[10] = ffma2(a1, wA.x, acc[10]);
                        acc[1] = ffma2(a0, wA.y, acc[1]);  acc[11] = ffma2(a1, wA.y, acc[11]);
                        acc[2] = ffma2(a0, wB.x, acc[2]);  acc[12] = ffma2(a1, wB.x, acc[12]);
                        acc[3] = ffma2(a0, wB.y, acc[3]);  acc[13] = ffma2(a1, wB.y, acc[13]);
                        acc[4] = ffma2(a0, wC.x, acc[4]);  acc[14] = ffma2(a1, wC.x, acc[14]);
                        acc[5] = ffma2(a0, wC.y, acc[5]);  acc[15] = ffma2(a1, wC.y, acc[15]);
                        acc[6] = ffma2(a0, wD.x, acc[6]);  acc[16] = ffma2(a1, wD.x, acc[16]);
                        acc[7] = ffma2(a0, wD.y, acc[7]);  acc[17] = ffma2(a1, wD.y, acc[17]);
                        acc[8] = ffma2(a0, wE.x, acc[8]);  acc[18] = ffma2(a1, wE.x, acc[18]);
                        acc[9] = ffma2(a0, wE.y, acc[9]);  acc[19] = ffma2(a1, wE.y, acc[19]);
                    }
                    if (c < 15) {
                        float2* Ab = (float2*)(sm + SMA + ((c + 1) & 1) * 2048);
                        Ab[sidx]       = make_float2(v0.x, v0.y);
                        Ab[sidx + 64]  = make_float2(v0.z, v0.w);
                        Ab[sidx + 128] = make_float2(v1.x, v1.y);
                        Ab[sidx + 192] = make_float2(v1.z, v1.w);
                    }
                }
#pragma unroll
                for (int j = 0; j < 10; ++j) {
                    sm[SMC + lane * 81 + c0 + j]        = psum(acc[j]);
                    sm[SMC + (lane + 32) * 81 + c0 + j] = psum(acc[10 + j]);
                }
                __syncthreads();
                if (t <= 325) {
                    float* hn = g_h[(t + 1) & 1];
#pragma unroll
                    for (int j = 0; j < 5; ++j) {
                        int iu = eq + 4 * j;
                        if (iu < nU) {
                            int lc = iu * 4;
                            const float* Cr = sm + SMC + erow * 81 + lc;
                            const float* bb = sm + SMB + lc;
                            float vi = sigf(Cr[0] + bb[0]);
                            float vf = sigf(Cr[1] + bb[1]);
                            float vg = tanhf(Cr[2] + bb[2]);
                            float vo = sigf(Cr[3] + bb[3]);
                            int gx = (rb + erow) * 512 + ub + iu;
                            float cn = vf * g_c[gx] + vi * vg;
                            g_c[gx] = cn;
                            hn[gx] = vo * tanhf(cn);
                        }
                    }
                }
                if (nZ > 0) {
                    float* zn = g_zz[t & 1];
#pragma unroll
                    for (int j = 0; j < 20; ++j) {
                        int ic = eq + 4 * j;
                        if (ic < nZ) {
                            int lc = zlc0 + ic;
                            float v = sm[SMC + erow * 81 + lc] + sm[SMB + lc];
                            zn[(rb + erow) * 512 + (cb + lc - 2048)] = v > 0.f ? v : 0.f;
                        }
                    }
                }
            }
            gbar(t);
        }
    } else {
        // ---- y-CTAs: y(t-1) = z(t-1) @ W2^T + b2 ----
        float* Zs = sm; float* W2s = sm + 4160;   // Zs padded: [64][65]
        const int rbY = (ct - 128) * 64;
        const int r = tid & 63, s = tid >> 6;
        for (int i = tid; i < 4608; i += 256) W2s[i] = g_W2T[i];
        __syncthreads();
        for (int t = 1; t <= 327; ++t) {
            if (t >= 2) {
                const float* z = g_zz[(t - 1) & 1];
                float acc[3] = {0.f, 0.f, 0.f};
                for (int kc = 0; kc < 512; kc += 64) {
                    __syncthreads();
#pragma unroll
                    for (int h = 0; h < 4; ++h) {
                        int sl = s + h * 4;
                        float4 v = *(const float4*)(z + (rbY + r) * 512 + kc + sl * 4);
                        Zs[r * 65 + sl * 4 + 0] = v.x; Zs[r * 65 + sl * 4 + 1] = v.y;
                        Zs[r * 65 + sl * 4 + 2] = v.z; Zs[r * 65 + sl * 4 + 3] = v.w;
                    }
                    __syncthreads();
#pragma unroll
                    for (int pi = 0; pi < 3; ++pi) {
                        int p = tid + pi * 256;
                        if (p < 576) {
                            int rw = p / 9, o = p - rw * 9;
                            float a = acc[pi];
#pragma unroll 8
                            for (int k = 0; k < 64; ++k)
                                a += Zs[rw * 65 + k] * W2s[(kc + k) * 9 + o];
                            acc[pi] = a;
                        }
                    }
                }
#pragma unroll
                for (int pi = 0; pi < 3; ++pi) {
                    int p = tid + pi * 256;
                    if (p < 576) {
                        int rw = p / 9, o = p - rw * 9;
                        out[(rbY + rw) * 2934 + (t - 2) * 9 + o] = acc[pi] + b2[o];
                    }
                }
            }
            gbar(t);
        }
    }
}

// ---------------- launch -------------------------------------------------------
extern "C" void kernel_launch(void* const* d_in, const int* in_sizes, int n_in,
                              void* d_out, int out_size) {
    const float* x   = (const float*)d_in[0];
    const float* hx0 = (const float*)d_in[1];
    const float* cx0 = (const float*)d_in[2];
    const float* Wih = (const float*)d_in[3];
    const float* Whh = (const float*)d_in[4];
    const float* bih = (const float*)d_in[5];
    const float* bhh = (const float*)d_in[6];
    const float* W1  = (const float*)d_in[7];
    const float* b1  = (const float*)d_in[8];
    const float* W2  = (const float*)d_in[9];
    const float* b2  = (const float*)d_in[10];
    float* out = (float*)d_out;

    cudaFuncSetAttribute(main_kernel, cudaFuncAttributeMaxDynamicSharedMemorySize, SMEM_BYTES);

    prepB<<<28, 256>>>(bih, bhh, b1, W2);
    prepWpair<<<5120, 256>>>(Wih, Whh, W1);
    step0_kernel<<<128, 256>>>(x, hx0, cx0, Wih, Whh);
    main_kernel<<<NCTA, 256, SMEM_BYTES>>>(out, b2);
}

// round 7
// speedup vs baseline: 1.4059x; 1.1957x over previous
#include <cuda_runtime.h>
#include <math.h>

typedef unsigned long long ull;
#define NCTA 132
// dynamic smem layout (float offsets) for compute CTAs
#define SMA 40960                 // A buffers: 2 halves x 2 bufs x 2048 floats
#define SMC 49152                 // C tile 64 x 81
#define SMB 54336                 // bias 80
#define SMEM_BYTES ((54336 + 96) * 4)

// ---------------- persistent device state (no allocations) -----------------
__device__ float g_Wpair[512 * 2560];   // [kp][col*2+d]; cols 0..2047 gates (j'=4u+g), 2048..2559 W1
__device__ float g_ball[2560];
__device__ float g_W2T[512 * 9];
__device__ float g_h[2][256 * 512];
__device__ float g_c[256 * 512];
__device__ float g_zz[2][256 * 512];
__device__ unsigned g_arrive;
__device__ volatile unsigned g_epoch;

// ---------------- helpers ----------------------------------------------------
__device__ __forceinline__ ull ffma2(ull a, ull b, ull c) {
    ull d; asm("fma.rn.f32x2 %0,%1,%2,%3;" : "=l"(d) : "l"(a), "l"(b), "l"(c)); return d;
}
__device__ __forceinline__ float psum(ull v) {
    float lo, hi; asm("mov.b64 {%0,%1},%2;" : "=f"(lo), "=f"(hi) : "l"(v)); return lo + hi;
}
__device__ __forceinline__ float sigf(float v) { return 1.f / (1.f + expf(-v)); }

__device__ __forceinline__ void gbar(int p) {
    __syncthreads();
    if (threadIdx.x == 0) {
        __threadfence();
        unsigned prev = atomicAdd(&g_arrive, 1u);
        if (prev == NCTA - 1) {
            g_arrive = 0;
            __threadfence();
            g_epoch = (unsigned)p;
        } else {
            while (g_epoch < (unsigned)p) __nanosleep(32);
            __threadfence();
        }
    }
    __syncthreads();
}

// ---------------- prep kernels -----------------------------------------------
__global__ void prepWpair(const float* __restrict__ Wih, const float* __restrict__ Whh,
                          const float* __restrict__ W1) {
    int idx = blockIdx.x * 256 + threadIdx.x;        // 1,310,720
    int kp = idx / 5120, rem = idx - kp * 5120;
    int col = rem >> 1, d = rem & 1;
    int k = kp * 2 + d;
    float v;
    if (col < 2048) { int u = col >> 2, gi = col & 3, j = gi * 512 + u;
                      v = Wih[j * 512 + k] + Whh[j * 512 + k]; }
    else            { v = W1[(col - 2048) * 512 + k]; }
    g_Wpair[idx] = v;
}
__global__ void prepB(const float* __restrict__ bih, const float* __restrict__ bhh,
                      const float* __restrict__ b1, const float* __restrict__ W2) {
    int idx = blockIdx.x * 256 + threadIdx.x;        // 7168
    if (idx < 2048) { int u = idx >> 2, gi = idx & 3, j = gi * 512 + u;
                      g_ball[idx] = bih[j] + bhh[j]; }
    else if (idx < 2560) g_ball[idx] = b1[idx - 2048];
    else if (idx < 7168) { int i2 = idx - 2560; int k = i2 / 9, o = i2 - k * 9;
                           g_W2T[i2] = W2[o * 512 + k]; }
    if (idx == 0) { g_arrive = 0; g_epoch = 0; }
}

// ---------------- step 0: h(1), c(1) = cell(x, hx0, cx0), K=1024 --------------
__global__ void __launch_bounds__(256) step0_kernel(
    const float* __restrict__ x, const float* __restrict__ hx0,
    const float* __restrict__ cx0,
    const float* __restrict__ Wih, const float* __restrict__ Whh) {
    __shared__ __align__(16) float As[32 * 64];
    __shared__ __align__(16) float Wsm[32 * 64];
    const int tid = threadIdx.x, tx = tid & 15, ty = tid >> 4;
    const int ct = blockIdx.x, rb = (ct >> 5) << 6, cb = (ct & 31) << 6;
    const int r = tid & 63, s = tid >> 6;
    const int jc = cb + r, jrow = (jc & 3) * 512 + (jc >> 2);

    float acc[4][4] = {};
    for (int kc = 0; kc < 1024; kc += 32) {
        const float* Asrc = (kc < 512) ? x : hx0;
        const float* Wsrc = (kc < 512) ? Wih : Whh;
        const int kloc = (kc < 512) ? kc : kc - 512;
        __syncthreads();
#pragma unroll
        for (int h = 0; h < 2; ++h) {
            int sl = s + h * 4;
            float4 v = *(const float4*)(Asrc + (rb + r) * 512 + kloc + sl * 4);
            As[(sl * 4 + 0) * 64 + r] = v.x; As[(sl * 4 + 1) * 64 + r] = v.y;
            As[(sl * 4 + 2) * 64 + r] = v.z; As[(sl * 4 + 3) * 64 + r] = v.w;
            float4 w = *(const float4*)(Wsrc + jrow * 512 + kloc + sl * 4);
            Wsm[(sl * 4 + 0) * 64 + r] = w.x; Wsm[(sl * 4 + 1) * 64 + r] = w.y;
            Wsm[(sl * 4 + 2) * 64 + r] = w.z; Wsm[(sl * 4 + 3) * 64 + r] = w.w;
        }
        __syncthreads();
#pragma unroll 8
        for (int k = 0; k < 32; ++k) {
            float a0 = As[k * 64 + ty * 4 + 0], a1 = As[k * 64 + ty * 4 + 1];
            float a2 = As[k * 64 + ty * 4 + 2], a3 = As[k * 64 + ty * 4 + 3];
            float w0 = Wsm[k * 64 + tx * 4 + 0], w1 = Wsm[k * 64 + tx * 4 + 1];
            float w2 = Wsm[k * 64 + tx * 4 + 2], w3 = Wsm[k * 64 + tx * 4 + 3];
            acc[0][0] += a0 * w0; acc[0][1] += a0 * w1; acc[0][2] += a0 * w2; acc[0][3] += a0 * w3;
            acc[1][0] += a1 * w0; acc[1][1] += a1 * w1; acc[1][2] += a1 * w2; acc[1][3] += a1 * w3;
            acc[2][0] += a2 * w0; acc[2][1] += a2 * w1; acc[2][2] += a2 * w2; acc[2][3] += a2 * w3;
            acc[3][0] += a3 * w0; acc[3][1] += a3 * w1; acc[3][2] += a3 * w2; acc[3][3] += a3 * w3;
        }
    }
    const int u = (cb >> 2) + tx;
#pragma unroll
    for (int i = 0; i < 4; ++i) {
        int gx = (rb + ty * 4 + i) * 512 + u;
        float vi = sigf(acc[i][0] + g_ball[cb + tx * 4 + 0]);
        float vf = sigf(acc[i][1] + g_ball[cb + tx * 4 + 1]);
        float vg = tanhf(acc[i][2] + g_ball[cb + tx * 4 + 2]);
        float vo = sigf(acc[i][3] + g_ball[cb + tx * 4 + 3]);
        float cn = vf * cx0[gx] + vi * vg;
        g_c[gx] = cn;
        g_h[1][gx] = vo * tanhf(cn);
    }
}

// ---------------- persistent main kernel (512 threads, split-K) ---------------
__global__ void __launch_bounds__(512) main_kernel(float* __restrict__ out,
                                                   const float* __restrict__ b2) {
    extern __shared__ float sm[];
    const int tid = threadIdx.x, ct = blockIdx.x;

    if (ct < 128) {
        const int rb = (ct >> 5) << 6, cs = ct & 31, cb = cs * 80;
        const int half = tid >> 8, htid = tid & 255;
        const int lane = htid & 31, warp8 = htid >> 5, c0 = warp8 * 10;
        const int nU   = (cs < 25) ? 20 : (cs == 25 ? 12 : 0);
        const int zlc0 = (cs < 25) ? 80 : (cs == 25 ? 48 : 0);
        const int nZ = 80 - zlc0;
        const int erow = tid >> 3, eq = tid & 7, ub = cb >> 2;
        const int rr = htid >> 2, kq = (htid & 3) * 8;
        const int sidx = (htid & 3) * 4 * 64 + rr;
        float* Abase = sm + SMA + half * 4096;      // this half's A double buffer

        // one-time: load W tile (80 cols x 256 kp, k-pair layout) into smem
        for (int i = tid; i < 10240; i += 512) {
            int kp = i / 40, off = i - kp * 40;
            ((float4*)sm)[kp * 40 + off] =
                ((const float4*)(g_Wpair + kp * 5120 + cb * 2))[off];
        }
        if (tid < 80) sm[SMB + tid] = g_ball[cb + tid];
        __syncthreads();

        for (int t = 1; t <= 327; ++t) {
            if (t <= 326 && (t <= 325 || nZ > 0)) {
                // each half covers 8 chunks of 32 k (16 kp); half1 starts at k=256
                const float* hc = g_h[t & 1] + (rb + rr) * 512 + half * 256 + kq;
                ull acc[20];
#pragma unroll
                for (int i = 0; i < 20; ++i) acc[i] = 0ull;

                float4 v0 = *(const float4*)(hc);
                float4 v1 = *(const float4*)(hc + 4);
                {
                    float2* Ab = (float2*)Abase;
                    Ab[sidx]       = make_float2(v0.x, v0.y);
                    Ab[sidx + 64]  = make_float2(v0.z, v0.w);
                    Ab[sidx + 128] = make_float2(v1.x, v1.y);
                    Ab[sidx + 192] = make_float2(v1.z, v1.w);
                }
                for (int c = 0; c < 8; ++c) {
                    __syncthreads();
                    if (c < 7) {
                        v0 = *(const float4*)(hc + (c + 1) * 32);
                        v1 = *(const float4*)(hc + (c + 1) * 32 + 4);
                    }
                    const ull* Ap = (const ull*)(Abase + (c & 1) * 2048);
                    const float* Wb = sm + (half * 128 + c * 16) * 160 + c0 * 2;
#pragma unroll
                    for (int kp = 0; kp < 16; ++kp) {
                        ull a0 = Ap[kp * 64 + lane];
                        ull a1 = Ap[kp * 64 + 32 + lane];
                        const ulonglong2* Wp = (const ulonglong2*)(Wb + kp * 160);
                        ulonglong2 wA = Wp[0], wB = Wp[1], wC = Wp[2], wD = Wp[3], wE = Wp[4];
                        acc[0] = ffma2(a0, wA.x, acc[0]);  acc[10] = ffma2(a1, wA.x, acc[10]);
                        acc[1] = ffma2(a0, wA.y, acc[1]);  acc[11] = ffma2(a1, wA.y, acc[11]);
                        acc[2] = ffma2(a0, wB.x, acc[2]);  acc[12] = ffma2(a1, wB.x, acc[12]);
                        acc[3] = ffma2(a0, wB.y, acc[3]);  acc[13] = ffma2(a1, wB.y, acc[13]);
                        acc[4] = ffma2(a0, wC.x, acc[4]);  acc[14] = ffma2(a1, wC.x, acc[14]);
                        acc[5] = ffma2(a0, wC.y, acc[5]);  acc[15] = ffma2(a1, wC.y, acc[15]);
                        acc[6] = ffma2(a0, wD.x, acc[6]);  acc[16] = ffma2(a1, wD.x, acc[16]);
                        acc[7] = ffma2(a0, wD.y, acc[7]);  acc[17] = ffma2(a1, wD.y, acc[17]);
                        acc[8] = ffma2(a0, wE.x, acc[8]);  acc[18] = ffma2(a1, wE.x, acc[18]);
                        acc[9] = ffma2(a0, wE.y, acc[9]);  acc[19] = ffma2(a1, wE.y, acc[19]);
                    }
                    if (c < 7) {
                        float2* Ab = (float2*)(Abase + ((c + 1) & 1) * 2048);
                        Ab[sidx]       = make_float2(v0.x, v0.y);
                        Ab[sidx + 64]  = make_float2(v0.z, v0.w);
                        Ab[sidx + 128] = make_float2(v1.x, v1.y);
                        Ab[sidx + 192] = make_float2(v1.z, v1.w);
                    }
                }
                // merge split-K halves into C tile
                if (half == 0) {
#pragma unroll
                    for (int j = 0; j < 10; ++j) {
                        sm[SMC + lane * 81 + c0 + j]        = psum(acc[j]);
                        sm[SMC + (lane + 32) * 81 + c0 + j] = psum(acc[10 + j]);
                    }
                }
                __syncthreads();
                if (half == 1) {
#pragma unroll
                    for (int j = 0; j < 10; ++j) {
                        sm[SMC + lane * 81 + c0 + j]        += psum(acc[j]);
                        sm[SMC + (lane + 32) * 81 + c0 + j] += psum(acc[10 + j]);
                    }
                }
                __syncthreads();
                if (t <= 325) {
                    float* hn = g_h[(t + 1) & 1];
#pragma unroll
                    for (int j = 0; j < 3; ++j) {
                        int iu = eq + 8 * j;
                        if (iu < nU) {
                            int lc = iu * 4;
                            const float* Cr = sm + SMC + erow * 81 + lc;
                            const float* bb = sm + SMB + lc;
                            float vi = sigf(Cr[0] + bb[0]);
                            float vf = sigf(Cr[1] + bb[1]);
                            float vg = tanhf(Cr[2] + bb[2]);
                            float vo = sigf(Cr[3] + bb[3]);
                            int gx = (rb + erow) * 512 + ub + iu;
                            float cn = vf * g_c[gx] + vi * vg;
                            g_c[gx] = cn;
                            hn[gx] = vo * tanhf(cn);
                        }
                    }
                }
                if (nZ > 0) {
                    float* zn = g_zz[t & 1];
#pragma unroll
                    for (int j = 0; j < 10; ++j) {
                        int ic = eq + 8 * j;
                        if (ic < nZ) {
                            int lc = zlc0 + ic;
                            float v = sm[SMC + erow * 81 + lc] + sm[SMB + lc];
                            zn[(rb + erow) * 512 + (cb + lc - 2048)] = v > 0.f ? v : 0.f;
                        }
                    }
                }
            }
            gbar(t);
        }
    } else {
        // ---- y-CTAs: y(t-1) = z(t-1) @ W2^T + b2 ----
        float* Zs = sm; float* W2s = sm + 4160;   // Zs padded: [64][65]
        const int rbY = (ct - 128) * 64;
        const int r = tid & 63, s = tid >> 6;     // s in 0..7
        for (int i = tid; i < 4608; i += 512) W2s[i] = g_W2T[i];
        __syncthreads();
        for (int t = 1; t <= 327; ++t) {
            if (t >= 2) {
                const float* z = g_zz[(t - 1) & 1];
                float acc2[2] = {0.f, 0.f};
                for (int kc = 0; kc < 512; kc += 64) {
                    __syncthreads();
#pragma unroll
                    for (int h = 0; h < 2; ++h) {
                        int sl = s + h * 8;
                        float4 v = *(const float4*)(z + (rbY + r) * 512 + kc + sl * 4);
                        Zs[r * 65 + sl * 4 + 0] = v.x; Zs[r * 65 + sl * 4 + 1] = v.y;
                        Zs[r * 65 + sl * 4 + 2] = v.z; Zs[r * 65 + sl * 4 + 3] = v.w;
                    }
                    __syncthreads();
#pragma unroll
                    for (int pi = 0; pi < 2; ++pi) {
                        int p = tid + pi * 512;
                        if (p < 576) {
                            int rw = p / 9, o = p - rw * 9;
                            float a = acc2[pi];
#pragma unroll 8
                            for (int k = 0; k < 64; ++k)
                                a += Zs[rw * 65 + k] * W2s[(kc + k) * 9 + o];
                            acc2[pi] = a;
                        }
                    }
                }
#pragma unroll
                for (int pi = 0; pi < 2; ++pi) {
                    int p = tid + pi * 512;
                    if (p < 576) {
                        int rw = p / 9, o = p - rw * 9;
                        out[(rbY + rw) * 2934 + (t - 2) * 9 + o] = acc2[pi] + b2[o];
                    }
                }
            }
            gbar(t);
        }
    }
}

// ---------------- launch -------------------------------------------------------
extern "C" void kernel_launch(void* const* d_in, const int* in_sizes, int n_in,
                              void* d_out, int out_size) {
    const float* x   = (const float*)d_in[0];
    const float* hx0 = (const float*)d_in[1];
    const float* cx0 = (const float*)d_in[2];
    const float* Wih = (const float*)d_in[3];
    const float* Whh = (const float*)d_in[4];
    const float* bih = (const float*)d_in[5];
    const float* bhh = (const float*)d_in[6];
    const float* W1  = (const float*)d_in[7];
    const float* b1  = (const float*)d_in[8];
    const float* W2  = (const float*)d_in[9];
    const float* b2  = (const float*)d_in[10];
    float* out = (float*)d_out;

    cudaFuncSetAttribute(main_kernel, cudaFuncAttributeMaxDynamicSharedMemorySize, SMEM_BYTES);

    prepB<<<28, 256>>>(bih, bhh, b1, W2);
    prepWpair<<<5120, 256>>>(Wih, Whh, W1);
    step0_kernel<<<128, 256>>>(x, hx0, cx0, Wih, Whh);
    main_kernel<<<NCTA, 512, SMEM_BYTES>>>(out, b2);
}

// round 9
// speedup vs baseline: 1.4827x; 1.0547x over previous
#include <cuda_runtime.h>
#include <cuda_bf16.h>
#include <math.h>

typedef unsigned long long ull;
typedef unsigned int u32;

#define NCTA 132                 // 128 compute + 4 head
// dynamic smem byte offsets (compute CTAs)
#define OFF_WH 0                 // W hi fragments: 80KB
#define OFF_WL 81920             // W lo fragments: 80KB
#define OFF_A  163840            // A hi chunk: 64 rows x 136 bf16 (272B rows) = 17408B
#define OFF_AL 181248            // A lo chunk: 17408B
#define OFF_C  198656            // C tile 64 x 82 f32 = 20992B
#define OFF_BS 219648            // 80 bias floats
#define SMEM_BYTES 219968

// ---------------- persistent device state (no allocations) -----------------
// W fragments, per-lane register layout: [split][ (cb*10+ti)*32*32*2 + (kk*32+lane)*2 + reg ]
__device__ u32 g_Wfrag[2][655360];
__device__ __nv_bfloat16 g_hbf[2][2][256 * 512];   // [buf][hi/lo][row*512+u]
__device__ float g_ball[2560];                     // gate cols j'=4u+g, then b1
__device__ float g_W2T[512 * 9];
__device__ float g_c[256 * 512];
__device__ float g_zz[2][256 * 512];
__device__ unsigned g_arrive;
__device__ volatile unsigned g_epoch;

// ---------------- helpers ----------------------------------------------------
__device__ __forceinline__ float sigf(float v) { return 1.f / (1.f + expf(-v)); }
__device__ __forceinline__ void split_bf16(float v, __nv_bfloat16& hi, __nv_bfloat16& lo) {
    hi = __float2bfloat16_rn(v);
    lo = __float2bfloat16_rn(v - __bfloat162float(hi));
}
__device__ __forceinline__ u32 smem_u32(const void* p) {
    u32 a; asm("{ .reg .u64 t; cvta.to.shared.u64 t, %1; cvt.u32.u64 %0, t; }" : "=r"(a) : "l"(p));
    return a;
}
__device__ __forceinline__ void gbar(int p) {
    __syncthreads();
    if (threadIdx.x == 0) {
        __threadfence();
        if (atomicAdd(&g_arrive, 1u) == NCTA - 1) {
            g_arrive = 0;
            __threadfence();
            g_epoch = (unsigned)p;
        } else {
            while (g_epoch < (unsigned)p) __nanosleep(32);
            __threadfence();
        }
    }
    __syncthreads();
}
__device__ __forceinline__ void ldm4(u32 addr, u32& r0, u32& r1, u32& r2, u32& r3) {
    asm volatile("ldmatrix.sync.aligned.m8n8.x4.shared.b16 {%0,%1,%2,%3}, [%4];"
                 : "=r"(r0), "=r"(r1), "=r"(r2), "=r"(r3) : "r"(addr));
}
__device__ __forceinline__ void mma16816(float* d, u32 a0, u32 a1, u32 a2, u32 a3,
                                         u32 b0, u32 b1) {
    asm volatile("mma.sync.aligned.m16n8k16.row.col.f32.bf16.bf16.f32 "
                 "{%0,%1,%2,%3},{%4,%5,%6,%7},{%8,%9},{%0,%1,%2,%3};"
                 : "+f"(d[0]), "+f"(d[1]), "+f"(d[2]), "+f"(d[3])
                 : "r"(a0), "r"(a1), "r"(a2), "r"(a3), "r"(b0), "r"(b1));
}

// write h(fp32) as bf16 hi/lo, row-major
__device__ __forceinline__ void store_h(int buf, int row, int u, float v) {
    __nv_bfloat16 hi, lo; split_bf16(v, hi, lo);
    g_hbf[buf][0][row * 512 + u] = hi;
    g_hbf[buf][1][row * 512 + u] = lo;
}

// ---------------- prep kernels -----------------------------------------------
__device__ __forceinline__ float wall_val(const float* Wih, const float* Whh,
                                          const float* W1, int cs, int k) {
    if (cs < 2048) { int j = (cs & 3) * 512 + (cs >> 2);
                     return Wih[j * 512 + k] + Whh[j * 512 + k]; }
    return W1[(cs - 2048) * 512 + k];
}
__global__ void prepWfrag(const float* __restrict__ Wih, const float* __restrict__ Whh,
                          const float* __restrict__ W1) {
    int gid = blockIdx.x * 256 + threadIdx.x;       // 655,360 total
    int reg = gid & 1, lane = (gid >> 1) & 31, kk = (gid >> 6) & 31;
    int rem = gid >> 11, ti = rem % 10, cb = rem / 10;
    int cs = cb * 80 + ti * 8 + (lane >> 2);
    int k0 = kk * 16 + (lane & 3) * 2 + reg * 8;
    float v0 = wall_val(Wih, Whh, W1, cs, k0);
    float v1 = wall_val(Wih, Whh, W1, cs, k0 + 1);
    __nv_bfloat16 h0, l0, h1, l1;
    split_bf16(v0, h0, l0); split_bf16(v1, h1, l1);
    u32 hp = (u32)__bfloat16_as_ushort(h0) | ((u32)__bfloat16_as_ushort(h1) << 16);
    u32 lp = (u32)__bfloat16_as_ushort(l0) | ((u32)__bfloat16_as_ushort(l1) << 16);
    g_Wfrag[0][gid] = hp;
    g_Wfrag[1][gid] = lp;
}
__global__ void prepB(const float* __restrict__ bih, const float* __restrict__ bhh,
                      const float* __restrict__ b1, const float* __restrict__ W2) {
    int idx = blockIdx.x * 256 + threadIdx.x;       // 7168
    if (idx < 2048) { int u = idx >> 2, gi = idx & 3, j = gi * 512 + u;
                      g_ball[idx] = bih[j] + bhh[j]; }
    else if (idx < 2560) g_ball[idx] = b1[idx - 2048];
    else if (idx < 7168) { int i2 = idx - 2560; int k = i2 / 9, o = i2 - k * 9;
                           g_W2T[i2] = W2[o * 512 + k]; }
    if (idx == 0) { g_arrive = 0; g_epoch = 0; }
}

// ---------------- step 0: h(1), c(1) = cell(x, hx0, cx0), K=1024 --------------
__global__ void __launch_bounds__(256) step0_kernel(
    const float* __restrict__ x, const float* __restrict__ hx0,
    const float* __restrict__ cx0,
    const float* __restrict__ Wih, const float* __restrict__ Whh) {
    __shared__ __align__(16) float As[32 * 64];
    __shared__ __align__(16) float Wsm[32 * 64];
    const int tid = threadIdx.x, tx = tid & 15, ty = tid >> 4;
    const int ct = blockIdx.x, rb = (ct >> 5) << 6, cb = (ct & 31) << 6;
    const int r = tid & 63, s = tid >> 6;
    const int jc = cb + r, jrow = (jc & 3) * 512 + (jc >> 2);

    float acc[4][4] = {};
    for (int kc = 0; kc < 1024; kc += 32) {
        const float* Asrc = (kc < 512) ? x : hx0;
        const float* Wsrc = (kc < 512) ? Wih : Whh;
        const int kloc = (kc < 512) ? kc : kc - 512;
        __syncthreads();
#pragma unroll
        for (int h = 0; h < 2; ++h) {
            int sl = s + h * 4;
            float4 v = *(const float4*)(Asrc + (rb + r) * 512 + kloc + sl * 4);
            As[(sl * 4 + 0) * 64 + r] = v.x; As[(sl * 4 + 1) * 64 + r] = v.y;
            As[(sl * 4 + 2) * 64 + r] = v.z; As[(sl * 4 + 3) * 64 + r] = v.w;
            float4 w = *(const float4*)(Wsrc + jrow * 512 + kloc + sl * 4);
            Wsm[(sl * 4 + 0) * 64 + r] = w.x; Wsm[(sl * 4 + 1) * 64 + r] = w.y;
            Wsm[(sl * 4 + 2) * 64 + r] = w.z; Wsm[(sl * 4 + 3) * 64 + r] = w.w;
        }
        __syncthreads();
#pragma unroll 8
        for (int k = 0; k < 32; ++k) {
            float a0 = As[k * 64 + ty * 4 + 0], a1 = As[k * 64 + ty * 4 + 1];
            float a2 = As[k * 64 + ty * 4 + 2], a3 = As[k * 64 + ty * 4 + 3];
            float w0 = Wsm[k * 64 + tx * 4 + 0], w1 = Wsm[k * 64 + tx * 4 + 1];
            float w2 = Wsm[k * 64 + tx * 4 + 2], w3 = Wsm[k * 64 + tx * 4 + 3];
            acc[0][0] += a0 * w0; acc[0][1] += a0 * w1; acc[0][2] += a0 * w2; acc[0][3] += a0 * w3;
            acc[1][0] += a1 * w0; acc[1][1] += a1 * w1; acc[1][2] += a1 * w2; acc[1][3] += a1 * w3;
            acc[2][0] += a2 * w0; acc[2][1] += a2 * w1; acc[2][2] += a2 * w2; acc[2][3] += a2 * w3;
            acc[3][0] += a3 * w0; acc[3][1] += a3 * w1; acc[3][2] += a3 * w2; acc[3][3] += a3 * w3;
        }
    }
    const int u = (cb >> 2) + tx;
#pragma unroll
    for (int i = 0; i < 4; ++i) {
        int row = rb + ty * 4 + i;
        int gx = row * 512 + u;
        float vi = sigf(acc[i][0] + g_ball[cb + tx * 4 + 0]);
        float vf = sigf(acc[i][1] + g_ball[cb + tx * 4 + 1]);
        float vg = tanhf(acc[i][2] + g_ball[cb + tx * 4 + 2]);
        float vo = sigf(acc[i][3] + g_ball[cb + tx * 4 + 3]);
        float cn = vf * cx0[gx] + vi * vg;
        g_c[gx] = cn;
        store_h(1, row, u, vo * tanhf(cn));
    }
}

// ---------------- persistent main kernel --------------------------------------
__global__ void __launch_bounds__(256, 1) main_kernel(float* __restrict__ out,
                                                      const float* __restrict__ b2) {
    extern __shared__ __align__(16) float smf[];
    char* smc = (char*)smf;
    const int tid = threadIdx.x, ct = blockIdx.x;

    if (ct < 128) {
        const int rb = (ct >> 5) << 6, cs = ct & 31, cb = cs * 80;
        const int lane = tid & 31, wid = tid >> 5;
        const int wr = wid & 3, wc = wid >> 2;          // warp: rows wr*16, cols wc*40
        const int nU   = (cs < 25) ? 20 : (cs == 25 ? 12 : 0);
        const int zlc0 = (cs < 25) ? 80 : (cs == 25 ? 48 : 0);
        const int nZ = 80 - zlc0;
        const int erow = tid >> 2, eq = tid & 3, ub = cb >> 2;
        const int ar = tid >> 2, aseg = tid & 3;
        const u32 smb = smem_u32(smf);

        // one-time: resident W fragment tiles (hi, lo)
        {
            const uint4* sH = (const uint4*)(g_Wfrag[0] + cs * 20480);
            const uint4* sL = (const uint4*)(g_Wfrag[1] + cs * 20480);
            uint4* dH = (uint4*)(smc + OFF_WH);
            uint4* dL = (uint4*)(smc + OFF_WL);
#pragma unroll
            for (int i = 0; i < 20; ++i) {
                dH[tid + i * 256] = sH[tid + i * 256];
                dL[tid + i * 256] = sL[tid + i * 256];
            }
        }
        if (tid < 80) smf[OFF_BS / 4 + tid] = g_ball[cb + tid];
        __syncthreads();

        // per-lane ldmatrix source offsets within A tile (272B row stride)
        const u32 arow = (u32)(wr * 16 + (lane & 7) + ((lane >> 3) & 1) * 8);
        const u32 aoffH = smb + OFF_A  + arow * 272 + ((lane >> 4) & 1) * 16;
        const u32 aoffL = smb + OFF_AL + arow * 272 + ((lane >> 4) & 1) * 16;
        // W fragment base (u32 index) for this warp's 5 tiles
        const u32* WHp = (const u32*)(smc + OFF_WH);
        const u32* WLp = (const u32*)(smc + OFF_WL);

        for (int t = 1; t <= 327; ++t) {
            const bool isGate = nU > 0, hasZ = nZ > 0;
            if (t <= 326 && ((t <= 325 && isGate) || hasZ)) {
                float acc[5][4];
#pragma unroll
                for (int j = 0; j < 5; ++j)
#pragma unroll
                    for (int i = 0; i < 4; ++i) acc[j][i] = 0.f;

                const __nv_bfloat16* hH = g_hbf[t & 1][0] + (rb + ar) * 512 + aseg * 32;
                const __nv_bfloat16* hL = g_hbf[t & 1][1] + (rb + ar) * 512 + aseg * 32;

                for (int ch = 0; ch < 4; ++ch) {
                    __syncthreads();
                    {
                        const uint4* gH = (const uint4*)(hH + ch * 128);
                        const uint4* gL = (const uint4*)(hL + ch * 128);
                        uint4* dH = (uint4*)(smc + OFF_A  + ar * 272 + aseg * 64);
                        uint4* dL = (uint4*)(smc + OFF_AL + ar * 272 + aseg * 64);
#pragma unroll
                        for (int j = 0; j < 4; ++j) { dH[j] = gH[j]; dL[j] = gL[j]; }
                    }
                    __syncthreads();
#pragma unroll
                    for (int kk = 0; kk < 8; ++kk) {
                        u32 aH0, aH1, aH2, aH3, aL0, aL1, aL2, aL3;
                        ldm4(aoffH + kk * 32, aH0, aH1, aH2, aH3);
                        ldm4(aoffL + kk * 32, aL0, aL1, aL2, aL3);
                        const int kg = ch * 8 + kk;
#pragma unroll
                        for (int j = 0; j < 5; ++j) {
                            const u32 widx = (((wc * 5 + j) * 32 + kg) * 32 + lane) * 2;
                            u32 bH0 = WHp[widx], bH1 = WHp[widx + 1];
                            u32 bL0 = WLp[widx], bL1 = WLp[widx + 1];
                            mma16816(acc[j], aH0, aH1, aH2, aH3, bH0, bH1);
                            mma16816(acc[j], aH0, aH1, aH2, aH3, bL0, bL1);
                            mma16816(acc[j], aL0, aL1, aL2, aL3, bH0, bH1);
                        }
                    }
                }
                // D fragments -> C tile in smem (stride 82 floats)
                {
                    const int drow = wr * 16 + (lane >> 2);
                    const int dcol = wc * 40 + (lane & 3) * 2;
                    float* C0 = smf + OFF_C / 4 + drow * 82 + dcol;
                    float* C1 = smf + OFF_C / 4 + (drow + 8) * 82 + dcol;
#pragma unroll
                    for (int j = 0; j < 5; ++j) {
                        *(float2*)(C0 + j * 8) = make_float2(acc[j][0], acc[j][1]);
                        *(float2*)(C1 + j * 8) = make_float2(acc[j][2], acc[j][3]);
                    }
                }
                __syncthreads();

                const float* Cr = smf + OFF_C / 4 + erow * 82;
                const float* bb = smf + OFF_BS / 4;
                if (t <= 325 && isGate) {
                    const int nbuf = (t + 1) & 1;
#pragma unroll
                    for (int j = 0; j < 5; ++j) {
                        int iu = eq + 4 * j;
                        if (iu < nU) {
                            int lc = iu * 4;
                            float vi = sigf(Cr[lc + 0] + bb[lc + 0]);
                            float vf = sigf(Cr[lc + 1] + bb[lc + 1]);
                            float vg = tanhf(Cr[lc + 2] + bb[lc + 2]);
                            float vo = sigf(Cr[lc + 3] + bb[lc + 3]);
                            int gx = (rb + erow) * 512 + ub + iu;
                            float cn = vf * g_c[gx] + vi * vg;
                            g_c[gx] = cn;
                            store_h(nbuf, rb + erow, ub + iu, vo * tanhf(cn));
                        }
                    }
                }
                if (hasZ) {
                    float* zn = g_zz[t & 1];
#pragma unroll
                    for (int j = 0; j < 20; ++j) {
                        int ic = eq + 4 * j;
                        if (ic < nZ) {
                            int lc = zlc0 + ic;
                            float v = Cr[lc] + bb[lc];
                            zn[(rb + erow) * 512 + (cb + lc - 2048)] = v > 0.f ? v : 0.f;
                        }
                    }
                }
            }
            gbar(t);
        }
    } else {
        // ---- y-CTAs: y(t-1) = z(t-1) @ W2^T + b2 ----
        float* Zs = smf; float* W2s = smf + 4160;   // Zs padded: [64][65]
        const int rbY = (ct - 128) * 64;
        const int r = tid & 63, s = tid >> 6;
        for (int i = tid; i < 4608; i += 256) W2s[i] = g_W2T[i];
        __syncthreads();
        for (int t = 1; t <= 327; ++t) {
            if (t >= 2) {
                const float* z = g_zz[(t - 1) & 1];
                float acc[3] = {0.f, 0.f, 0.f};
                for (int kc = 0; kc < 512; kc += 64) {
                    __syncthreads();
#pragma unroll
                    for (int h = 0; h < 4; ++h) {
                        int sl = s + h * 4;
                        float4 v = *(const float4*)(z + (rbY + r) * 512 + kc + sl * 4);
                        Zs[r * 65 + sl * 4 + 0] = v.x; Zs[r * 65 + sl * 4 + 1] = v.y;
                        Zs[r * 65 + sl * 4 + 2] = v.z; Zs[r * 65 + sl * 4 + 3] = v.w;
                    }
                    __syncthreads();
#pragma unroll
                    for (int pi = 0; pi < 3; ++pi) {
                        int p = tid + pi * 256;
                        if (p < 576) {
                            int rw = p / 9, o = p - rw * 9;
                            float a = acc[pi];
#pragma unroll 8
                            for (int k = 0; k < 64; ++k)
                                a += Zs[rw * 65 + k] * W2s[(kc + k) * 9 + o];
                            acc[pi] = a;
                        }
                    }
                }
#pragma unroll
                for (int pi = 0; pi < 3; ++pi) {
                    int p = tid + pi * 256;
                    if (p < 576) {
                        int rw = p / 9, o = p - rw * 9;
                        out[(rbY + rw) * 2934 + (t - 2) * 9 + o] = acc[pi] + b2[o];
                    }
                }
            }
            gbar(t);
        }
    }
}

// ---------------- launch -------------------------------------------------------
extern "C" void kernel_launch(void* const* d_in, const int* in_sizes, int n_in,
                              void* d_out, int out_size) {
    const float* x   = (const float*)d_in[0];
    const float* hx0 = (const float*)d_in[1];
    const float* cx0 = (const float*)d_in[2];
    const float* Wih = (const float*)d_in[3];
    const float* Whh = (const float*)d_in[4];
    const float* bih = (const float*)d_in[5];
    const float* bhh = (const float*)d_in[6];
    const float* W1  = (const float*)d_in[7];
    const float* b1  = (const float*)d_in[8];
    const float* W2  = (const float*)d_in[9];
    const float* b2  = (const float*)d_in[10];
    float* out = (float*)d_out;

    cudaFuncSetAttribute(main_kernel, cudaFuncAttributeMaxDynamicSharedMemorySize, SMEM_BYTES);

    prepB<<<28, 256>>>(bih, bhh, b1, W2);
    prepWfrag<<<2560, 256>>>(Wih, Whh, W1);
    step0_kernel<<<128, 256>>>(x, hx0, cx0, Wih, Whh);
    main_kernel<<<NCTA, 256, SMEM_BYTES>>>(out, b2);
}